// round 6
// baseline (speedup 1.0000x reference)
#include <cuda_runtime.h>

#define NN 100000
#define HH 64
#define EMAX 1600000
#define BN_EPS 1e-5f

// ---- scratch (static device globals) ----
__device__ float4 g_bufA[NN * HH / 4];   // hs (scaled features)
__device__ float4 g_bufB[NN * HH / 4];   // layer output
__device__ int   g_csr[EMAX];            // src ids grouped by dst
__device__ int   g_cnt[NN];              // in-degree
__device__ int   g_off[NN];              // CSR offsets
__device__ int   g_cur[NN];              // placement cursor
__device__ int   g_is64;
__device__ float g_dinv[NN];
// stats padded: channel ch at [ch*32] -> own 128B line
__device__ float g_stats1[128 * 32];
__device__ float g_stats2[128 * 32];
__device__ float g_bn1[128];             // a[64], c[64]
__device__ float g_bn2[128];

// ---- init: zero counts+stats; block 0 detects int64 vs int32 edge_index ----
__global__ void k_init(const unsigned int* __restrict__ ei) {
    int i = blockIdx.x * 256 + threadIdx.x;
    if (i < NN) g_cnt[i] = 0;
    if (i < 128 * 32) { g_stats1[i] = 0.0f; g_stats2[i] = 0.0f; }
    if (blockIdx.x == 0) {
        __shared__ unsigned int s;
        if (threadIdx.x == 0) s = 0u;
        __syncthreads();
        atomicOr(&s, ei[threadIdx.x * 2 + 1]);  // high words if int64
        __syncthreads();
        if (threadIdx.x == 0) g_is64 = (s == 0u) ? 1 : 0;
    }
}

// ---- in-degree of dst ----
__global__ void k_deg(const void* __restrict__ ei, int E) {
    int e = blockIdx.x * 256 + threadIdx.x;
    if (e >= E) return;
    int d = g_is64 ? (int)((const long long*)ei)[E + e] : ((const int*)ei)[E + e];
    atomicAdd(&g_cnt[d], 1);
}

// ---- single-block scan: offsets, cursor copy, dinv ----
__global__ void __launch_bounds__(1024) k_scan() {
    __shared__ int psum[1024];
    const int t = threadIdx.x;
    const int C = (NN + 1023) / 1024;
    int lo = t * C, hi = min(lo + C, NN);
    int s = 0;
    for (int i = lo; i < hi; i++) s += g_cnt[i];
    psum[t] = s;
    __syncthreads();
    for (int off = 1; off < 1024; off <<= 1) {
        int v = (t >= off) ? psum[t - off] : 0;
        __syncthreads();
        psum[t] += v;
        __syncthreads();
    }
    int run = (t == 0) ? 0 : psum[t - 1];
    for (int i = lo; i < hi; i++) {
        int c = g_cnt[i];
        g_off[i] = run;
        g_cur[i] = run;
        g_dinv[i] = rsqrtf((float)c + 1.0f);   // +1 self loop
        run += c;
    }
}

// ---- CSR placement: bucket src by dst ----
__global__ void k_place(const void* __restrict__ ei, int E) {
    int e = blockIdx.x * 256 + threadIdx.x;
    if (e >= E) return;
    int s, d;
    if (g_is64) {
        const long long* p = (const long long*)ei;
        s = (int)p[e]; d = (int)p[E + e];
    } else {
        const int* p = (const int*)ei;
        s = p[e]; d = p[E + e];
    }
    int pos = atomicAdd(&g_cur[d], 1);
    g_csr[pos] = s;
}

// ---- GEMM: out[r] = ((a*X[r]+c) @ W) * rowscale[r] + (bias + c@W) ----
template <int NOUT>
__global__ void __launch_bounds__(128) k_gemm(
    const float* __restrict__ X, const float* __restrict__ Wg,
    const float* __restrict__ bn, const float* __restrict__ rowscale,
    const float* __restrict__ bias, float* __restrict__ out)
{
    extern __shared__ float sm[];
    float* Xs   = sm;                 // 128 * 65
    float* Ws   = sm + 128 * 65;      // 64 * NOUT (pre-scaled by a[k])
    float* Init = Ws + 64 * NOUT;     // NOUT

    const int t = threadIdx.x;
    const long row0 = (long)blockIdx.x * 128;

    #pragma unroll
    for (int i = 0; i < 16; i++) {
        int lin = t + i * 128;
        int r = lin >> 4, q = lin & 15;
        long gr = row0 + r;
        float4 v = (gr < NN) ? reinterpret_cast<const float4*>(X)[gr * 16 + q]
                             : make_float4(0.f, 0.f, 0.f, 0.f);
        float* p = &Xs[r * 65 + q * 4];
        p[0] = v.x; p[1] = v.y; p[2] = v.z; p[3] = v.w;
    }
    #pragma unroll
    for (int i = t; i < 16 * NOUT; i += 128) {
        int k = (i * 4) / NOUT;
        float a = bn ? bn[k] : 1.0f;
        float4 w = reinterpret_cast<const float4*>(Wg)[i];
        reinterpret_cast<float4*>(Ws)[i] = make_float4(w.x * a, w.y * a, w.z * a, w.w * a);
    }
    if (t < NOUT) {
        float s = bias ? bias[t] : 0.0f;
        if (bn) {
            #pragma unroll 8
            for (int k = 0; k < 64; k++) s += bn[64 + k] * Wg[k * NOUT + t];
        }
        Init[t] = s;
    }
    __syncthreads();

    unsigned long long acc[NOUT / 2];
    #pragma unroll
    for (int j = 0; j < NOUT / 2; j++) {
        float2 iv = reinterpret_cast<const float2*>(Init)[j];
        asm("mov.b64 %0, {%1, %2};" : "=l"(acc[j]) : "f"(iv.x), "f"(iv.y));
    }
    const float* xr = &Xs[t * 65];
    #pragma unroll 4
    for (int k = 0; k < 64; k++) {
        float xv = xr[k];
        unsigned long long xx;
        asm("mov.b64 %0, {%1, %1};" : "=l"(xx) : "f"(xv));
        const unsigned long long* wr =
            reinterpret_cast<const unsigned long long*>(&Ws[k * NOUT]);
        #pragma unroll
        for (int j = 0; j < NOUT / 2; j++)
            asm("fma.rn.f32x2 %0, %1, %2, %0;" : "+l"(acc[j]) : "l"(xx), "l"(wr[j]));
    }

    long r = row0 + t;
    float rs = 1.0f;
    if (rowscale && r < NN) rs = rowscale[r];

    __syncthreads();
    #pragma unroll
    for (int j = 0; j < NOUT / 2; j++) {
        float lo, hi;
        asm("mov.b64 {%0, %1}, %2;" : "=f"(lo), "=f"(hi) : "l"(acc[j]));
        Xs[t * 65 + 2 * j]     = lo * rs;
        Xs[t * 65 + 2 * j + 1] = hi * rs;
    }
    __syncthreads();
    constexpr int Q = NOUT / 4;
    #pragma unroll
    for (int i = 0; i < Q; i++) {
        int lin = t + i * 128;
        int r2 = lin / Q, q = lin % Q;
        long gr = row0 + r2;
        if (gr < NN) {
            float* p = &Xs[r2 * 65 + q * 4];
            reinterpret_cast<float4*>(out)[gr * Q + q] = make_float4(p[0], p[1], p[2], p[3]);
        }
    }
}

// ---- fused CSR gather + epilogue: 16 threads per node, thread=(v,q) ----
// out[v] = relu(dinv[v]*(hs[v]+sum_{s in CSR[v]} hs[s]) + bias); BN stats.
__global__ void __launch_bounds__(256) k_agg(
    const float4* __restrict__ hs, float4* __restrict__ out,
    const float* __restrict__ bias, float* __restrict__ stats)
{
    __shared__ float ssum[64], ssq[64];
    const int t = threadIdx.x;
    if (t < 64) { ssum[t] = 0.0f; ssq[t] = 0.0f; }
    __syncthreads();
    long idx = (long)blockIdx.x * 256 + t;
    if (idx < (long)NN * 16) {
        const int v = (int)(idx >> 4);
        const int q = (int)(idx & 15);
        const int base = g_off[v];
        const int d = g_cnt[v];
        float4 acc = hs[(long)v * 16 + q];   // self-loop term
        int j = 0;
        for (; j + 4 <= d; j += 4) {
            int s0 = g_csr[base + j];
            int s1 = g_csr[base + j + 1];
            int s2 = g_csr[base + j + 2];
            int s3 = g_csr[base + j + 3];
            float4 a0 = hs[(long)s0 * 16 + q];
            float4 a1 = hs[(long)s1 * 16 + q];
            float4 a2 = hs[(long)s2 * 16 + q];
            float4 a3 = hs[(long)s3 * 16 + q];
            acc.x += (a0.x + a1.x) + (a2.x + a3.x);
            acc.y += (a0.y + a1.y) + (a2.y + a3.y);
            acc.z += (a0.z + a1.z) + (a2.z + a3.z);
            acc.w += (a0.w + a1.w) + (a2.w + a3.w);
        }
        for (; j < d; j++) {
            int s0 = g_csr[base + j];
            float4 a0 = hs[(long)s0 * 16 + q];
            acc.x += a0.x; acc.y += a0.y; acc.z += a0.z; acc.w += a0.w;
        }
        const float di = g_dinv[v];
        const float4 b = reinterpret_cast<const float4*>(bias)[q];
        float4 o;
        o.x = fmaxf(fmaf(di, acc.x, b.x), 0.0f);
        o.y = fmaxf(fmaf(di, acc.y, b.y), 0.0f);
        o.z = fmaxf(fmaf(di, acc.z, b.z), 0.0f);
        o.w = fmaxf(fmaf(di, acc.w, b.w), 0.0f);
        out[(long)v * 16 + q] = o;
        int c = q * 4;
        atomicAdd(&ssum[c + 0], o.x); atomicAdd(&ssq[c + 0], o.x * o.x);
        atomicAdd(&ssum[c + 1], o.y); atomicAdd(&ssq[c + 1], o.y * o.y);
        atomicAdd(&ssum[c + 2], o.z); atomicAdd(&ssq[c + 2], o.z * o.z);
        atomicAdd(&ssum[c + 3], o.w); atomicAdd(&ssq[c + 3], o.w * o.w);
    }
    __syncthreads();
    if (t < 64) {
        atomicAdd(&stats[t * 32], ssum[t]);
        atomicAdd(&stats[(64 + t) * 32], ssq[t]);
    }
}

// ---- BN coefficients: a = gamma*rsqrt(var+eps), c = beta - mu*a ----
__global__ void k_bn(const float* __restrict__ stats, const float* __restrict__ gamma,
                     const float* __restrict__ beta, float* __restrict__ bn)
{
    int j = threadIdx.x;
    if (j < 64) {
        float mu  = stats[j * 32] * (1.0f / NN);
        float var = stats[(64 + j) * 32] * (1.0f / NN) - mu * mu;
        float a = gamma[j] * rsqrtf(var + BN_EPS);
        bn[j] = a;
        bn[64 + j] = beta[j] - mu * a;
    }
}

extern "C" void kernel_launch(void* const* d_in, const int* in_sizes, int n_in,
                              void* d_out, int out_size)
{
    const float* x      = (const float*)d_in[0];
    const void*  ei     = d_in[1];
    const float* W1     = (const float*)d_in[2];
    const float* b1     = (const float*)d_in[3];
    const float* gamma1 = (const float*)d_in[4];
    const float* beta1  = (const float*)d_in[5];
    const float* W2     = (const float*)d_in[6];
    const float* b2     = (const float*)d_in[7];
    const float* gamma2 = (const float*)d_in[8];
    const float* beta2  = (const float*)d_in[9];
    const float* Wfc    = (const float*)d_in[10];
    const float* bfc    = (const float*)d_in[11];
    float* out = (float*)d_out;

    int E = in_sizes[1] / 2;
    if (E > EMAX) E = EMAX;

    float4 *pA, *pB;
    float *ps1, *ps2, *pbn1, *pbn2, *pdinv;
    cudaGetSymbolAddress((void**)&pA, g_bufA);
    cudaGetSymbolAddress((void**)&pB, g_bufB);
    cudaGetSymbolAddress((void**)&ps1, g_stats1);
    cudaGetSymbolAddress((void**)&ps2, g_stats2);
    cudaGetSymbolAddress((void**)&pbn1, g_bn1);
    cudaGetSymbolAddress((void**)&pbn2, g_bn2);
    cudaGetSymbolAddress((void**)&pdinv, g_dinv);

    const int smem64 = (128 * 65 + 64 * 64 + 64) * (int)sizeof(float);
    const int smem32 = (128 * 65 + 64 * 32 + 32) * (int)sizeof(float);
    cudaFuncSetAttribute(k_gemm<64>, cudaFuncAttributeMaxDynamicSharedMemorySize, smem64);
    cudaFuncSetAttribute(k_gemm<32>, cudaFuncAttributeMaxDynamicSharedMemorySize, smem32);

    const int GB = (NN + 127) / 128;
    const int EB = (E + 255) / 256;
    const int AB = (NN * 16 + 255) / 256;   // 6250

    k_init<<<(NN + 255) / 256, 256>>>((const unsigned int*)ei);
    k_deg<<<EB, 256>>>(ei, E);
    k_scan<<<1, 1024>>>();
    k_place<<<EB, 256>>>(ei, E);

    // layer 1: hs1 = (x@W1)*dinv -> CSR agg + relu + stats -> h1
    k_gemm<64><<<GB, 128, smem64>>>(x, W1, nullptr, pdinv, nullptr, (float*)pA);
    k_agg<<<AB, 256>>>(pA, pB, b1, ps1);       // launch #5 -> profiled
    k_bn<<<1, 64>>>(ps1, gamma1, beta1, pbn1);

    // layer 2
    k_gemm<64><<<GB, 128, smem64>>>((const float*)pB, W2, pbn1, pdinv, nullptr, (float*)pA);
    k_agg<<<AB, 256>>>(pA, pB, b2, ps2);
    k_bn<<<1, 64>>>(ps2, gamma2, beta2, pbn2);

    // final
    k_gemm<32><<<GB, 128, smem32>>>((const float*)pB, Wfc, pbn2, nullptr, bfc, out);
}